// round 11
// baseline (speedup 1.0000x reference)
#include <cuda_runtime.h>
#include <cuda.h>
#include <stdint.h>

#define BB   256          // batch (images / segments)
#define DD   512          // embedding dim
#define HWQ  256          // H*W spatial positions
#define NT   256          // threads per block
#define DH   256          // d-half size (DD/2)
#define DH4  64           // float4s per half-vector
#define D4   128          // float4s per full vector

__device__ __forceinline__ uint32_t smem_u32(const void* p) {
    uint32_t a;
    asm("{ .reg .u64 t; cvta.to.shared.u64 t, %1; cvt.u32.u64 %0, t; }"
        : "=r"(a) : "l"(p));
    return a;
}
__device__ __forceinline__ void bulk_store(void* gdst, uint32_t ssrc, uint32_t bytes) {
    asm volatile("cp.async.bulk.global.shared::cta.bulk_group [%0], [%1], %2;"
                 :: "l"(gdst), "r"(ssrc), "r"(bytes) : "memory");
}
__device__ __forceinline__ void tensor_store_2d(const CUtensorMap* tmap,
                                                int x, int y, uint32_t ssrc) {
    asm volatile("cp.async.bulk.tensor.2d.global.shared::cta.tile.bulk_group "
                 "[%0, {%1, %2}], [%3];"
                 :: "l"(tmap), "r"(x), "r"(y), "r"(ssrc) : "memory");
}
__device__ __forceinline__ void bulk_commit() {
    asm volatile("cp.async.bulk.commit_group;" ::: "memory");
}
__device__ __forceinline__ void bulk_wait0() {
    asm volatile("cp.async.bulk.wait_group 0;" ::: "memory");
}

// ---------------------------------------------------------------------------
// 768 blocks x 256 threads, single wave (<=8 blocks/SM).
//   bid in [0,256)    : snd item b. Scan splits in-smem (dtype-robust),
//                       reduce full segment b (256 KiB read), replicate the
//                       2 KiB vector 8x in smem, write M_snd[b,:,:] (512 KiB
//                       contiguous) as 32 x 16 KiB bulk stores.
//   bid in [256,768)  : img item (j,h). Reduce d-rows [256h,+256) of Z_img[j]
//                       (256 KiB read), replicate the 1 KiB half-vector 16x,
//                       write M_img[i,j,256h:+256) for all i as 16 tensor-TMA
//                       2D stores (box 256x16 = 16 strided rows = 16 KiB/op).
//                       Fallback (no tensormap): 256 x 1 KiB bulk stores.
// Output layout: [ M_img (B,B,D) | M_snd (B,B,D) ].
// ---------------------------------------------------------------------------
__global__ __launch_bounds__(NT, 8)
void fused_meanpool_bcast(const float* __restrict__ Zimg,
                          const float* __restrict__ Zsnd,
                          const int*   __restrict__ splits,
                          float*       __restrict__ out,
                          long long T,
                          const __grid_constant__ CUtensorMap tmap_img,
                          int use_tmap) {
    __shared__ long long s_scan[BB];                    // 2 KiB (snd only)
    __shared__ float4    s_part[2][D4];                 // 4 KiB (snd only)
    __shared__ __align__(16) float s_rep[16 * DH];      // 16 KiB replica image
    __shared__ __align__(16) float s_half[DH];          // 1 KiB (img only)

    const int t    = threadIdx.x;
    const int wid  = t >> 5;
    const int lane = t & 31;
    const size_t NIMG = (size_t)BB * BB * DD;           // floats in M_img

    if (blockIdx.x < BB) {
        // =================== SND ITEM (full d) ===================
        const int b = blockIdx.x;

        // --- in-block inclusive scan of splits (dtype-robust) ---
        s_scan[t] = (long long)splits[t];
        __syncthreads();
#pragma unroll
        for (int off = 1; off < BB; off <<= 1) {
            long long v = (t >= off) ? s_scan[t - off] : 0LL;
            __syncthreads();
            s_scan[t] += v;
            __syncthreads();
        }
        if (s_scan[BB - 1] != T) {
            const long long* p64 = (const long long*)splits;
            __syncthreads();
            s_scan[t] = p64[t];
            __syncthreads();
#pragma unroll
            for (int off = 1; off < BB; off <<= 1) {
                long long v = (t >= off) ? s_scan[t - off] : 0LL;
                __syncthreads();
                s_scan[t] += v;
                __syncthreads();
            }
        }
        __syncthreads();
        const long long start = (b == 0) ? 0LL : s_scan[b - 1];
        const long long len   = s_scan[b] - start;

        // --- reduce full vector: 2 row-slices x 128 float4 columns ---
        const int col   = t & (D4 - 1);                 // 0..127
        const int slice = t >> 7;                       // 0..1
        long long r0 = start + (len * slice)       / 2;
        long long r1 = start + (len * (slice + 1)) / 2;

        const float4* p = reinterpret_cast<const float4*>(Zsnd);
        float4 acc = make_float4(0.f, 0.f, 0.f, 0.f);
        for (long long r = r0; r < r1; ++r) {
            float4 v = __ldcs(&p[r * D4 + col]);
            acc.x += v.x; acc.y += v.y; acc.z += v.z; acc.w += v.w;
        }
        s_part[slice][col] = acc;
        __syncthreads();

        if (slice == 0) {
            float4 a0 = s_part[0][col], a1 = s_part[1][col];
            float inv = (len > 0) ? (1.0f / (float)len) : 0.0f;
            float4 o;
            o.x = (a0.x + a1.x) * inv;
            o.y = (a0.y + a1.y) * inv;
            o.z = (a0.z + a1.z) * inv;
            o.w = (a0.w + a1.w) * inv;
            // replicate 8x -> 16 KiB image (8 x 512-float vectors)
            float4* rp = reinterpret_cast<float4*>(s_rep);
#pragma unroll
            for (int k = 0; k < 8; ++k)
                rp[k * D4 + col] = o;
        }
        __syncthreads();
        asm volatile("fence.proxy.async.shared::cta;" ::: "memory");

        // --- 32 x 16 KiB contiguous bulk stores (8 issuers x 4 ops) ---
        if (lane == 0) {
            uint32_t src = smem_u32(s_rep);
            char* dst = (char*)(out + NIMG + (size_t)b * BB * DD);
            const uint32_t CSZ = 16384;
#pragma unroll
            for (int k = 0; k < 4; ++k)
                bulk_store(dst + (size_t)(wid * 4 + k) * CSZ, src, CSZ);
            bulk_commit();
            bulk_wait0();
        }

    } else {
        // =================== IMG ITEM (j, d-half h) ===================
        const int id = blockIdx.x - BB;
        const int j  = id >> 1;
        const int h  = id & 1;

        const float4* p = reinterpret_cast<const float4*>(
            Zimg + ((size_t)j * DD + (size_t)h * DH) * HWQ);

        // 8 warps x 32 rows; per row 64 float4, 2 per lane
        for (int k = 0; k < 32; ++k) {
            int lr = wid * 32 + k;
            float4 a = __ldcs(&p[(size_t)lr * 64 + lane]);
            float4 b = __ldcs(&p[(size_t)lr * 64 + 32 + lane]);
            float s = (a.x + a.y) + (a.z + a.w) + (b.x + b.y) + (b.z + b.w);
#pragma unroll
            for (int o = 16; o > 0; o >>= 1)
                s += __shfl_down_sync(0xffffffffu, s, o);
            if (lane == 0)
                s_half[lr] = s * (1.0f / (float)HWQ);
        }
        __syncthreads();

        // replicate 16x -> 16 KiB box image (16 rows x 256 floats)
        {
            const int c  = t & (DH4 - 1);               // 0..63
            const int s4 = t >> 6;                      // 0..3
            float4 v = reinterpret_cast<const float4*>(s_half)[c];
            float4* rp = reinterpret_cast<float4*>(s_rep);
#pragma unroll
            for (int k = 0; k < 4; ++k)
                rp[(s4 * 4 + k) * DH4 + c] = v;
        }
        __syncthreads();
        asm volatile("fence.proxy.async.shared::cta;" ::: "memory");

        if (use_tmap) {
            // 16 tensor-TMA 2D stores: box [256 floats x 16 rows] each
            if (lane == 0 && wid < 8) {
                uint32_t src = smem_u32(s_rep);
                const int x = j * DD + h * DH;
#pragma unroll
                for (int k = 0; k < 2; ++k) {
                    int y = (wid * 2 + k) * 16;         // i-row group
                    tensor_store_2d(&tmap_img, x, y, src);
                }
                bulk_commit();
                bulk_wait0();
            }
        } else {
            // fallback: 256 x 1 KiB bulk stores
            if (lane == 0) {
                uint32_t src = smem_u32(s_rep);         // first 1 KiB = half-vec
                char* dst0 = (char*)out + ((size_t)j * DD + (size_t)h * DH) * 4;
                const size_t STR = (size_t)BB * DD * 4; // 512 KiB
#pragma unroll 4
                for (int k = 0; k < 32; ++k) {
                    int i = wid * 32 + k;
                    bulk_store(dst0 + (size_t)i * STR, src, DH * 4);
                }
                bulk_commit();
                bulk_wait0();
            }
        }
    }
}

// ---------------------------------------------------------------------------
typedef CUresult (*tmap_encode_fn)(
    CUtensorMap*, CUtensorMapDataType, cuuint32_t, void*,
    const cuuint64_t*, const cuuint64_t*, const cuuint32_t*, const cuuint32_t*,
    CUtensorMapInterleave, CUtensorMapSwizzle, CUtensorMapL2promotion,
    CUtensorMapFloatOOBfill);

extern "C" void kernel_launch(void* const* d_in, const int* in_sizes, int n_in,
                              void* d_out, int out_size) {
    // Identify inputs by element count:
    //   Z_img: 33,554,432   Z_snd: 16,777,216   splits: 256
    const float* Zimg   = nullptr;
    const float* Zsnd   = nullptr;
    const int*   splits = nullptr;
    long long    Tsnd   = 0;

    for (int i = 0; i < n_in; ++i) {
        if (in_sizes[i] == BB) {
            splits = (const int*)d_in[i];
        } else if (in_sizes[i] == BB * DD * HWQ) {
            Zimg = (const float*)d_in[i];
        } else {
            Zsnd = (const float*)d_in[i];
            Tsnd = (long long)(in_sizes[i] / DD);
        }
    }
    (void)out_size;

    // Build 2D tensormap for M_img via driver entry point (no -lcuda link).
    CUtensorMap tmap{};
    int use_tmap = 0;
    {
        void* fp = nullptr;
        cudaDriverEntryPointQueryResult qr;
        if (cudaGetDriverEntryPoint("cuTensorMapEncodeTiled", &fp,
                                    cudaEnableDefault, &qr) == cudaSuccess &&
            fp != nullptr) {
            // M_img as 2D: dim0 = BB*DD floats per i-row, dim1 = BB rows
            cuuint64_t gdim[2]    = {(cuuint64_t)BB * DD, (cuuint64_t)BB};
            cuuint64_t gstride[1] = {(cuuint64_t)BB * DD * 4};  // bytes
            cuuint32_t box[2]     = {256, 16};
            cuuint32_t estr[2]    = {1, 1};
            CUresult r = ((tmap_encode_fn)fp)(
                &tmap, CU_TENSOR_MAP_DATA_TYPE_FLOAT32, 2, d_out,
                gdim, gstride, box, estr,
                CU_TENSOR_MAP_INTERLEAVE_NONE, CU_TENSOR_MAP_SWIZZLE_NONE,
                CU_TENSOR_MAP_L2_PROMOTION_L2_128B,
                CU_TENSOR_MAP_FLOAT_OOB_FILL_NONE);
            use_tmap = (r == CUDA_SUCCESS) ? 1 : 0;
        }
    }

    fused_meanpool_bcast<<<3 * BB, NT>>>(Zimg, Zsnd, splits,
                                         (float*)d_out, Tsnd,
                                         tmap, use_tmap);
}

// round 12
// speedup vs baseline: 1.0290x; 1.0290x over previous
#include <cuda_runtime.h>
#include <stdint.h>

#define BB   256          // batch (images / segments)
#define DD   512          // embedding dim
#define HWQ  256          // H*W spatial positions
#define NT   256          // threads per block
#define DH   256          // d-half size (DD/2)
#define DH4  64           // float4s per half-vector

__device__ __forceinline__ uint32_t smem_u32(const void* p) {
    uint32_t a;
    asm("{ .reg .u64 t; cvta.to.shared.u64 t, %1; cvt.u32.u64 %0, t; }"
        : "=r"(a) : "l"(p));
    return a;
}
__device__ __forceinline__ void bulk_store(void* gdst, uint32_t ssrc, uint32_t bytes) {
    asm volatile("cp.async.bulk.global.shared::cta.bulk_group [%0], [%1], %2;"
                 :: "l"(gdst), "r"(ssrc), "r"(bytes) : "memory");
}
__device__ __forceinline__ void bulk_commit() {
    asm volatile("cp.async.bulk.commit_group;" ::: "memory");
}
__device__ __forceinline__ void bulk_wait0() {
    asm volatile("cp.async.bulk.wait_group 0;" ::: "memory");
}

// ---------------------------------------------------------------------------
// 1024 uniform blocks x 256 threads, single wave at 8 blocks/SM.
// Item mapping interleaves types so each SM gets an even img/snd mix:
//   type = bid & 1, item = bid >> 1.
//   type 0 (img): item = (j,h): j = item>>1, h = item&1.
//       reduce d-rows [256h,+256) of Z_img[j]  (256 KiB contiguous read),
//       TMA-bulk-write M_img[i, j, 256h:+256) for all i (256 x 1 KiB rows,
//       stride 512 KiB).
//   type 1 (snd): item = (b,h): b = item>>1, h = item&1.
//       scan splits in-smem (dtype-robust), reduce cols [256h,+256) of
//       segment b (128 KiB read), TMA-bulk-write M_snd[b, :, 256h:+256)
//       (256 x 1 KiB rows, stride 2 KiB).
// Output layout: [ M_img (B,B,D) | M_snd (B,B,D) ].
// ---------------------------------------------------------------------------
__global__ __launch_bounds__(NT, 8)
void fused_meanpool_bcast(const float* __restrict__ Zimg,
                          const float* __restrict__ Zsnd,
                          const int*   __restrict__ splits,
                          float*       __restrict__ out,
                          long long T) {
    __shared__ long long s_scan[BB];                   // 2 KiB (snd only)
    __shared__ float4    s_part[4][DH4];               // 4 KiB (snd only)
    __shared__ __align__(16) float s_half[DH];         // 1 KiB half-vector

    const int t    = threadIdx.x;
    const int wid  = t >> 5;
    const int lane = t & 31;
    const int item = blockIdx.x >> 1;
    const int typ  = blockIdx.x & 1;
    const size_t NIMG = (size_t)BB * BB * DD;          // floats in M_img

    if (typ == 0) {
        // =================== IMG ITEM ===================
        const int j = item >> 1;
        const int h = item & 1;

        // rows [256h, 256h+256): contiguous 256 KiB slab
        const float4* p = reinterpret_cast<const float4*>(
            Zimg + ((size_t)j * DD + (size_t)h * DH) * HWQ);

        // 8 warps x 32 rows each; per row: 64 float4, 2 per lane
        for (int k = 0; k < 32; ++k) {
            int lr = wid * 32 + k;                     // local d-row 0..255
            float4 a = __ldcs(&p[(size_t)lr * 64 + lane]);
            float4 b = __ldcs(&p[(size_t)lr * 64 + 32 + lane]);
            float s = (a.x + a.y) + (a.z + a.w) + (b.x + b.y) + (b.z + b.w);
#pragma unroll
            for (int o = 16; o > 0; o >>= 1)
                s += __shfl_down_sync(0xffffffffu, s, o);
            if (lane == 0)
                s_half[lr] = s * (1.0f / (float)HWQ);
        }
        __syncthreads();
        asm volatile("fence.proxy.async.shared::cta;" ::: "memory");

        // write 256 rows x 1 KiB at 512 KiB stride
        if (lane == 0) {
            uint32_t src = smem_u32(s_half);
            char* dst0 = (char*)out + ((size_t)j * DD + (size_t)h * DH) * 4;
            const size_t STR = (size_t)BB * DD * 4;    // 512 KiB
#pragma unroll 4
            for (int k = 0; k < 32; ++k) {
                int i = wid * 32 + k;
                bulk_store(dst0 + (size_t)i * STR, src, DH * 4);
            }
            bulk_commit();
            bulk_wait0();
        }

    } else {
        // =================== SND ITEM ===================
        const int b = item >> 1;
        const int h = item & 1;

        // --- in-block inclusive scan of splits (dtype-robust) ---
        s_scan[t] = (long long)splits[t];
        __syncthreads();
#pragma unroll
        for (int off = 1; off < BB; off <<= 1) {
            long long v = (t >= off) ? s_scan[t - off] : 0LL;
            __syncthreads();
            s_scan[t] += v;
            __syncthreads();
        }
        if (s_scan[BB - 1] != T) {
            const long long* p64 = (const long long*)splits;
            __syncthreads();
            s_scan[t] = p64[t];
            __syncthreads();
#pragma unroll
            for (int off = 1; off < BB; off <<= 1) {
                long long v = (t >= off) ? s_scan[t - off] : 0LL;
                __syncthreads();
                s_scan[t] += v;
                __syncthreads();
            }
        }
        __syncthreads();
        const long long start = (b == 0) ? 0LL : s_scan[b - 1];
        const long long len   = s_scan[b] - start;

        // --- reduce cols [64h..64h+64) float4 over segment rows ---
        const int col   = t & (DH4 - 1);               // 0..63
        const int slice = t >> 6;                      // 0..3
        long long r0 = start + (len * slice)       / 4;
        long long r1 = start + (len * (slice + 1)) / 4;

        const float4* p = reinterpret_cast<const float4*>(Zsnd);
        // two accumulators, unroll x2 for deeper MLP
        float4 acc0 = make_float4(0.f, 0.f, 0.f, 0.f);
        float4 acc1 = make_float4(0.f, 0.f, 0.f, 0.f);
        long long r = r0;
        for (; r + 1 < r1; r += 2) {
            float4 v0 = __ldcs(&p[r       * (DD / 4) + h * DH4 + col]);
            float4 v1 = __ldcs(&p[(r + 1) * (DD / 4) + h * DH4 + col]);
            acc0.x += v0.x; acc0.y += v0.y; acc0.z += v0.z; acc0.w += v0.w;
            acc1.x += v1.x; acc1.y += v1.y; acc1.z += v1.z; acc1.w += v1.w;
        }
        if (r < r1) {
            float4 v0 = __ldcs(&p[r * (DD / 4) + h * DH4 + col]);
            acc0.x += v0.x; acc0.y += v0.y; acc0.z += v0.z; acc0.w += v0.w;
        }
        acc0.x += acc1.x; acc0.y += acc1.y; acc0.z += acc1.z; acc0.w += acc1.w;
        s_part[slice][col] = acc0;
        __syncthreads();

        if (slice == 0) {
            float4 a0 = s_part[0][col], a1 = s_part[1][col],
                   a2 = s_part[2][col], a3 = s_part[3][col];
            float inv = (len > 0) ? (1.0f / (float)len) : 0.0f;
            float4 o;
            o.x = (a0.x + a1.x + a2.x + a3.x) * inv;
            o.y = (a0.y + a1.y + a2.y + a3.y) * inv;
            o.z = (a0.z + a1.z + a2.z + a3.z) * inv;
            o.w = (a0.w + a1.w + a2.w + a3.w) * inv;
            reinterpret_cast<float4*>(s_half)[col] = o;
        }
        __syncthreads();
        asm volatile("fence.proxy.async.shared::cta;" ::: "memory");

        // write 256 rows x 1 KiB at 2 KiB stride
        if (lane == 0) {
            uint32_t src = smem_u32(s_half);
            char* dst0 = (char*)out + (NIMG
                       + (size_t)b * BB * DD + (size_t)h * DH) * 4;
            const size_t STR = (size_t)DD * 4;         // 2 KiB
#pragma unroll 4
            for (int k = 0; k < 32; ++k) {
                int i = wid * 32 + k;
                bulk_store(dst0 + (size_t)i * STR, src, DH * 4);
            }
            bulk_commit();
            bulk_wait0();
        }
    }
}

// ---------------------------------------------------------------------------
extern "C" void kernel_launch(void* const* d_in, const int* in_sizes, int n_in,
                              void* d_out, int out_size) {
    // Identify inputs by element count:
    //   Z_img: 33,554,432   Z_snd: 16,777,216   splits: 256
    const float* Zimg   = nullptr;
    const float* Zsnd   = nullptr;
    const int*   splits = nullptr;
    long long    Tsnd   = 0;

    for (int i = 0; i < n_in; ++i) {
        if (in_sizes[i] == BB) {
            splits = (const int*)d_in[i];
        } else if (in_sizes[i] == BB * DD * HWQ) {
            Zimg = (const float*)d_in[i];
        } else {
            Zsnd = (const float*)d_in[i];
            Tsnd = (long long)(in_sizes[i] / DD);
        }
    }
    (void)out_size;

    fused_meanpool_bcast<<<1024, NT>>>(Zimg, Zsnd, splits,
                                       (float*)d_out, Tsnd);
}